// round 5
// baseline (speedup 1.0000x reference)
#include <cuda_runtime.h>
#include <cuda_bf16.h>

#define NN 100000
#define EE 1600000
#define IND 128
#define HIDD 128
#define EMBD 64
#define KCL 100
#define EPSV 1e-5f

// ---------------- scratch (device globals; no allocs allowed) ----------------
__device__ int   g_is64;
__device__ int   g_src[EE];
__device__ int   g_dst[EE];
__device__ int   g_count[NN];
__device__ int   g_rowptr[NN + 1];
__device__ int   g_cursor[NN];
__device__ int   g_csr[EE];                 // src ids grouped by dst
__device__ float g_dis[NN];
__device__ float g_G1[(size_t)NN * HIDD];   // dis[v] * (x@W1)[v]  (messages conv1)
__device__ float g_A1[(size_t)NN * HIDD];   // conv1 accumulator
__device__ float g_G2[(size_t)NN * EMBD];   // dis[v] * (relu_bn@W2)[v] (messages conv2)
__device__ float g_A2[(size_t)NN * EMBD];   // conv2 accumulator
__device__ float g_sum[HIDD];
__device__ float g_sumsq[HIDD];
__device__ float g_bnscale[HIDD];
__device__ float g_bnshift[HIDD];

// ---------------- edge dtype detection + extraction ----------------
// If the buffer is int64 node-ids (< 2^31, >= 0), every odd 32-bit word is 0.
// If it is int32 node-ids (uniform in [0, 100000)), sampled odd words are
// essentially never all zero. Only reads words < 2*EE (safe for both dtypes).
__global__ void k_detect(const int* __restrict__ w) {
    int any = 0;
    // 128 samples spread over the first 2*EE words
    for (int i = 0; i < 128; i++) {
        int idx = 2 * (i * (EE / 128) + 7) + 1;   // odd words only
        any |= w[idx];
    }
    g_is64 = (any == 0) ? 1 : 0;
}

__global__ void k_extract(const void* __restrict__ buf) {
    int e = blockIdx.x * blockDim.x + threadIdx.x;
    if (e >= EE) return;
    int s, d;
    if (g_is64) {
        const long long* p = (const long long*)buf;
        s = (int)p[e];
        d = (int)p[(size_t)EE + e];
    } else {
        const int* p = (const int*)buf;
        s = p[e];
        d = p[(size_t)EE + e];
    }
    // clamp so no atomic can ever leave bounds (wrong result beats a trap)
    g_src[e] = ((unsigned)s < NN) ? s : 0;
    g_dst[e] = ((unsigned)d < NN) ? d : 0;
}

// ---------------- CSR build ----------------
__global__ void k_zero() {
    int i = blockIdx.x * blockDim.x + threadIdx.x;
    if (i < NN) g_count[i] = 0;
    if (i < HIDD) { g_sum[i] = 0.0f; g_sumsq[i] = 0.0f; }
}

__global__ void k_count() {
    int e = blockIdx.x * blockDim.x + threadIdx.x;
    if (e < EE) atomicAdd(&g_count[g_dst[e]], 1);
}

// single block: exclusive scan of counts -> rowptr/cursor; dis = rsqrt(deg)
__global__ __launch_bounds__(1024) void k_scan() {
    __shared__ int bs[1024];
    const int t = threadIdx.x;
    const int CH = (NN + 1023) / 1024;
    const int start = t * CH;
    const int end = min(start + CH, NN);
    int s = 0;
    for (int i = start; i < end; i++) s += g_count[i];
    bs[t] = s;
    __syncthreads();
    for (int off = 1; off < 1024; off <<= 1) {
        int v = bs[t];
        int add = (t >= off) ? bs[t - off] : 0;
        __syncthreads();
        bs[t] = v + add;
        __syncthreads();
    }
    int run = (t > 0) ? bs[t - 1] : 0;
    for (int i = start; i < end; i++) {
        int c = g_count[i];
        g_rowptr[i] = run;
        g_cursor[i] = run;
        g_dis[i] = rsqrtf((float)(c + 1));   // +1 self loop
        run += c;
    }
    if (t == 1023) g_rowptr[NN] = run;
}

__global__ void k_fill() {
    int e = blockIdx.x * blockDim.x + threadIdx.x;
    if (e < EE) {
        int pos = atomicAdd(&g_cursor[g_dst[e]], 1);
        g_csr[pos] = g_src[e];
    }
}

// ---------------- GEMM1: G1[v] = dis[v]*(x[v] @ W1) ----------------
// tile 32 rows x 128 cols, k-chunked by 64. 256 threads: 4 rows x 4 cols each.
__global__ __launch_bounds__(256) void k_gemm1(const float* __restrict__ x,
                                               const float* __restrict__ W1) {
    __shared__ float Ws[64 * 128];   // 32 KB
    __shared__ float xs[32 * 64];    // 8 KB
    const int row0 = blockIdx.x * 32;
    const int tid = threadIdx.x;
    const int tx = tid & 31;         // col group: cols 4*tx..4*tx+3
    const int ty = tid >> 5;         // row group: rows ty + 8*r  (warp-uniform)

    float4 acc[4];
#pragma unroll
    for (int r = 0; r < 4; r++) acc[r] = make_float4(0.f, 0.f, 0.f, 0.f);

    for (int kc = 0; kc < 2; kc++) {
#pragma unroll
        for (int t = 0; t < 8; t++) {           // load W1 chunk [64 x 128]
            int f = tid + t * 256;              // 2048 float4
            int r = f >> 5, c = f & 31;
            *(float4*)&Ws[r * 128 + c * 4] =
                *(const float4*)&W1[(size_t)(kc * 64 + r) * 128 + c * 4];
        }
#pragma unroll
        for (int t = 0; t < 2; t++) {           // load x tile [32 x 64]
            int f = tid + t * 256;              // 512 float4
            int r = f >> 4, c = f & 15;
            *(float4*)&xs[r * 64 + c * 4] =
                *(const float4*)&x[(size_t)(row0 + r) * 128 + kc * 64 + c * 4];
        }
        __syncthreads();
#pragma unroll 8
        for (int k = 0; k < 64; k++) {
            float4 w = *(float4*)&Ws[k * 128 + tx * 4];
#pragma unroll
            for (int r = 0; r < 4; r++) {
                float xv = xs[(ty + r * 8) * 64 + k];   // warp-broadcast
                acc[r].x += xv * w.x; acc[r].y += xv * w.y;
                acc[r].z += xv * w.z; acc[r].w += xv * w.w;
            }
        }
        __syncthreads();
    }
#pragma unroll
    for (int r = 0; r < 4; r++) {
        int row = row0 + ty + r * 8;
        float dv = g_dis[row];
        float4 v = make_float4(acc[r].x * dv, acc[r].y * dv, acc[r].z * dv, acc[r].w * dv);
        *(float4*)&g_G1[(size_t)row * 128 + tx * 4] = v;
    }
}

// ------------- conv1 aggregate: warp per node, gather in-edges -------------
__global__ __launch_bounds__(256) void k_gather1() {
    int w = (blockIdx.x * blockDim.x + threadIdx.x) >> 5;
    if (w >= NN) return;
    const int lane = threadIdx.x & 31;
    const size_t col = lane * 4;
    float4 acc = *(const float4*)&g_G1[(size_t)w * 128 + col];  // self loop
    int j = g_rowptr[w];
    const int end = g_rowptr[w + 1];
    for (; j + 1 < end; j += 2) {
        int s0 = g_csr[j], s1 = g_csr[j + 1];
        float4 a = *(const float4*)&g_G1[(size_t)s0 * 128 + col];
        float4 b = *(const float4*)&g_G1[(size_t)s1 * 128 + col];
        acc.x += a.x + b.x; acc.y += a.y + b.y;
        acc.z += a.z + b.z; acc.w += a.w + b.w;
    }
    if (j < end) {
        int s0 = g_csr[j];
        float4 a = *(const float4*)&g_G1[(size_t)s0 * 128 + col];
        acc.x += a.x; acc.y += a.y; acc.z += a.z; acc.w += a.w;
    }
    *(float4*)&g_A1[(size_t)w * 128 + col] = acc;
}

// ---------------- BN stats over hpost = dis[v]*A1[v] + b1 ----------------
__global__ void k_bnstats(const float* __restrict__ b1) {
    int j = threadIdx.x;      // 128 features
    float bj = b1[j];
    float s = 0.f, sq = 0.f;
    for (int v = blockIdx.x; v < NN; v += gridDim.x) {
        float h = g_dis[v] * g_A1[(size_t)v * 128 + j] + bj;
        s += h; sq += h * h;
    }
    atomicAdd(&g_sum[j], s);
    atomicAdd(&g_sumsq[j], sq);
}

__global__ void k_bnfin(const float* __restrict__ gamma, const float* __restrict__ beta) {
    int j = threadIdx.x;
    float mu = g_sum[j] * (1.0f / NN);
    float var = g_sumsq[j] * (1.0f / NN) - mu * mu;
    float inv = rsqrtf(var + EPSV);
    float sc = gamma[j] * inv;
    g_bnscale[j] = sc;
    g_bnshift[j] = beta[j] - mu * sc;
}

// ---------------- fused BN+ReLU+GEMM2: G2[v]=dis[v]*(relu(bn(h))@W2) -------
__global__ __launch_bounds__(256) void k_gemm2(const float* __restrict__ b1,
                                               const float* __restrict__ W2) {
    __shared__ float W2s[128 * 64];  // 32 KB
    __shared__ float ys[32 * 128];   // 16 KB  -> 48 KB static total
    const int row0 = blockIdx.x * 32;
    const int tid = threadIdx.x;

#pragma unroll
    for (int t = 0; t < 8; t++) {    // load full W2 [128 x 64]
        int f = tid + t * 256;       // 2048 float4
        *(float4*)&W2s[f * 4] = *(const float4*)&W2[(size_t)f * 4];
    }
    // stage 1: y = relu(bn(dis*A1 + b1))
#pragma unroll
    for (int t = 0; t < 16; t++) {
        int idx = tid + t * 256;
        int r = idx >> 7, c = idx & 127;
        int row = row0 + r;
        float h = g_dis[row] * g_A1[(size_t)row * 128 + c] + b1[c];
        float y = g_bnscale[c] * h + g_bnshift[c];
        ys[idx] = fmaxf(y, 0.0f);
    }
    __syncthreads();

    const int tx = tid & 31;         // cols 2*tx, 2*tx+1
    const int ty = tid >> 5;         // rows ty + 8*r (warp-uniform)
    float2 acc[4];
#pragma unroll
    for (int r = 0; r < 4; r++) acc[r] = make_float2(0.f, 0.f);
#pragma unroll 8
    for (int k = 0; k < 128; k++) {
        float2 w = *(float2*)&W2s[k * 64 + tx * 2];
#pragma unroll
        for (int r = 0; r < 4; r++) {
            float yv = ys[(ty + r * 8) * 128 + k];   // warp-broadcast
            acc[r].x += yv * w.x; acc[r].y += yv * w.y;
        }
    }
#pragma unroll
    for (int r = 0; r < 4; r++) {
        int row = row0 + ty + r * 8;
        float dv = g_dis[row];
        float2 v = make_float2(acc[r].x * dv, acc[r].y * dv);
        *(float2*)&g_G2[(size_t)row * 64 + tx * 2] = v;
    }
}

// ------------- conv2 aggregate: warp per node, float2 per lane -------------
__global__ __launch_bounds__(256) void k_gather2() {
    int w = (blockIdx.x * blockDim.x + threadIdx.x) >> 5;
    if (w >= NN) return;
    const int lane = threadIdx.x & 31;
    const size_t col = lane * 2;
    float2 acc = *(const float2*)&g_G2[(size_t)w * 64 + col];   // self loop
    int j = g_rowptr[w];
    const int end = g_rowptr[w + 1];
    for (; j + 1 < end; j += 2) {
        int s0 = g_csr[j], s1 = g_csr[j + 1];
        float2 a = *(const float2*)&g_G2[(size_t)s0 * 64 + col];
        float2 b = *(const float2*)&g_G2[(size_t)s1 * 64 + col];
        acc.x += a.x + b.x; acc.y += a.y + b.y;
    }
    if (j < end) {
        int s0 = g_csr[j];
        float2 a = *(const float2*)&g_G2[(size_t)s0 * 64 + col];
        acc.x += a.x; acc.y += a.y;
    }
    *(float2*)&g_A2[(size_t)w * 64 + col] = acc;
}

// ---------------- emb + logits + softmax ----------------
__global__ __launch_bounds__(128) void k_final(const float* __restrict__ b2,
                                               const float* __restrict__ centers,
                                               const float* __restrict__ temp,
                                               float* __restrict__ out) {
    __shared__ float4 cs[KCL * 16];  // centers [100 x 64] = 25.6 KB
    int tid = threadIdx.x;
    for (int i = tid; i < KCL * 16; i += blockDim.x)
        cs[i] = ((const float4*)centers)[i];
    __syncthreads();

    float invT = 1.0f / temp[0];
    float* emb_out = out;
    float* soft_out = out + (size_t)NN * EMBD;

    for (int v = blockIdx.x * blockDim.x + tid; v < NN; v += gridDim.x * blockDim.x) {
        float dv = g_dis[v];
        float4 e[16];
#pragma unroll
        for (int i = 0; i < 16; i++) {
            float4 a = *(const float4*)&g_A2[(size_t)v * 64 + i * 4];
            float4 bb = *(const float4*)&b2[i * 4];
            e[i] = make_float4(dv * a.x + bb.x, dv * a.y + bb.y,
                               dv * a.z + bb.z, dv * a.w + bb.w);
            *(float4*)&emb_out[(size_t)v * 64 + i * 4] = e[i];
        }
        float logits[KCL];
        float m = -1e30f;
        for (int k = 0; k < KCL; k++) {
            float s = 0.f;
#pragma unroll
            for (int i = 0; i < 16; i++) {
                float4 c = cs[k * 16 + i];        // warp-uniform broadcast
                s += e[i].x * c.x + e[i].y * c.y + e[i].z * c.z + e[i].w * c.w;
            }
            s *= invT;
            logits[k] = s;
            m = fmaxf(m, s);
        }
        float sum = 0.f;
        for (int k = 0; k < KCL; k++) { float p = __expf(logits[k] - m); logits[k] = p; sum += p; }
        float r = 1.0f / sum;
        for (int k = 0; k < KCL; k++) soft_out[(size_t)v * KCL + k] = logits[k] * r;
    }
}

// ---------------- launch ----------------
extern "C" void kernel_launch(void* const* d_in, const int* in_sizes, int n_in,
                              void* d_out, int out_size) {
    const float* x       = (const float*)d_in[0];
    const void*  ei      = d_in[1];                 // int32 or int64 (detected)
    const float* W1      = (const float*)d_in[2];
    const float* b1      = (const float*)d_in[3];
    const float* gamma   = (const float*)d_in[4];
    const float* beta    = (const float*)d_in[5];
    const float* W2      = (const float*)d_in[6];
    const float* b2      = (const float*)d_in[7];
    const float* centers = (const float*)d_in[8];
    const float* temp    = (const float*)d_in[9];
    float* out = (float*)d_out;

    k_detect<<<1, 1>>>((const int*)ei);
    k_extract<<<(EE + 255) / 256, 256>>>(ei);
    k_zero  <<<(NN + 255) / 256, 256>>>();
    k_count <<<(EE + 255) / 256, 256>>>();
    k_scan  <<<1, 1024>>>();
    k_fill  <<<(EE + 255) / 256, 256>>>();
    k_gemm1 <<<NN / 32, 256>>>(x, W1);
    k_gather1<<<(NN * 32 + 255) / 256, 256>>>();   // warp per node
    k_bnstats<<<1024, 128>>>(b1);
    k_bnfin <<<1, 128>>>(gamma, beta);
    k_gemm2 <<<NN / 32, 256>>>(b1, W2);
    k_gather2<<<(NN * 32 + 255) / 256, 256>>>();
    k_final <<<(NN + 127) / 128, 128>>>(b2, centers, temp, out);
}

// round 8
// speedup vs baseline: 1.0013x; 1.0013x over previous
#include <cuda_runtime.h>
#include <cuda_bf16.h>

#define NN 100000
#define EE 1600000
#define IND 128
#define HIDD 128
#define EMBD 64
#define KCL 100
#define EPSV 1e-5f

typedef unsigned long long ull;

// ---------------- scratch (device globals; no allocs allowed) ----------------
__device__ int   g_is64;
__device__ int   g_src[EE];
__device__ int   g_dst[EE];
__device__ int   g_count[NN];
__device__ int   g_rowptr[NN + 1];
__device__ int   g_cursor[NN];
__device__ int   g_csr[EE];                 // src ids grouped by dst
__device__ float g_dis[NN];
__device__ float g_G1[(size_t)NN * HIDD];   // dis[v] * (x@W1)[v]
__device__ float g_A1[(size_t)NN * HIDD];   // conv1 accumulator
__device__ float g_G2[(size_t)NN * EMBD];   // dis[v] * (relu_bn@W2)[v]
__device__ float g_A2[(size_t)NN * EMBD];   // conv2 accumulator
__device__ float g_sum[HIDD];
__device__ float g_sumsq[HIDD];
__device__ float g_bnscale[HIDD];
__device__ float g_bnshift[HIDD];

// ---------------- packed f32x2 helpers (sm_103a FFMA2 path) ----------------
__device__ __forceinline__ void fma2(ull& d, ull a, ull b) {
    asm("fma.rn.f32x2 %0, %1, %2, %0;" : "+l"(d) : "l"(a), "l"(b));
}
__device__ __forceinline__ float2 unpack2(ull v) {
    float2 f;
    asm("mov.b64 {%0, %1}, %2;" : "=f"(f.x), "=f"(f.y) : "l"(v));
    return f;
}

// ---------------- detect dtype + zero counters ----------------
// int64 node-ids (< 2^31) have all-zero odd 32-bit words; int32 ids don't.
__global__ void k_detect_zero(const int* __restrict__ w) {
    int i = blockIdx.x * blockDim.x + threadIdx.x;
    if (i < NN) g_count[i] = 0;
    if (i < HIDD) { g_sum[i] = 0.0f; g_sumsq[i] = 0.0f; }
    if (i == 0) {
        int any = 0;
        for (int t = 0; t < 128; t++) {
            int idx = 2 * (t * (EE / 128) + 7) + 1;   // odd words only
            any |= w[idx];
        }
        g_is64 = (any == 0) ? 1 : 0;
    }
}

// ---------------- extract edges (normalize to int32) + count degrees -------
__global__ void k_extract_count(const void* __restrict__ buf) {
    int e = blockIdx.x * blockDim.x + threadIdx.x;
    if (e >= EE) return;
    int s, d;
    if (g_is64) {
        const long long* p = (const long long*)buf;
        s = (int)p[e];
        d = (int)p[(size_t)EE + e];
    } else {
        const int* p = (const int*)buf;
        s = p[e];
        d = p[(size_t)EE + e];
    }
    s = ((unsigned)s < NN) ? s : 0;   // clamp: wrong result beats a trap
    d = ((unsigned)d < NN) ? d : 0;
    g_src[e] = s;
    g_dst[e] = d;
    atomicAdd(&g_count[d], 1);
}

// single block: exclusive scan of counts -> rowptr/cursor; dis = rsqrt(deg)
__global__ __launch_bounds__(1024) void k_scan() {
    __shared__ int bs[1024];
    const int t = threadIdx.x;
    const int CH = (NN + 1023) / 1024;
    const int start = t * CH;
    const int end = min(start + CH, NN);
    int s = 0;
    for (int i = start; i < end; i++) s += g_count[i];
    bs[t] = s;
    __syncthreads();
    for (int off = 1; off < 1024; off <<= 1) {
        int v = bs[t];
        int add = (t >= off) ? bs[t - off] : 0;
        __syncthreads();
        bs[t] = v + add;
        __syncthreads();
    }
    int run = (t > 0) ? bs[t - 1] : 0;
    for (int i = start; i < end; i++) {
        int c = g_count[i];
        g_rowptr[i] = run;
        g_cursor[i] = run;
        g_dis[i] = rsqrtf((float)(c + 1));   // +1 self loop
        run += c;
    }
    if (t == 1023) g_rowptr[NN] = run;
}

__global__ void k_fill() {
    int e = blockIdx.x * blockDim.x + threadIdx.x;
    if (e < EE) {
        int pos = atomicAdd(&g_cursor[g_dst[e]], 1);
        g_csr[pos] = g_src[e];
    }
}

// ---------------- GEMM1: G1[v] = dis[v]*(x[v] @ W1)  (f32x2 FMA) ----------
// tile 32 rows x 128 cols, k-chunk 64. 256 threads; thread: 4 rows x 4 cols
// (two column pairs at tx*2 and 64+tx*2). x staged duplicated so the
// broadcast operand is a direct LDS.64.
__global__ __launch_bounds__(256) void k_gemm1(const float* __restrict__ x,
                                               const float* __restrict__ W1) {
    __shared__ float Ws[64 * 128];    // 32 KB
    __shared__ float xs2[32 * 128];   // 16 KB (each x value duplicated)
    const int row0 = blockIdx.x * 32;
    const int tid = threadIdx.x;
    const int tx = tid & 31;
    const int ty = tid >> 5;          // warp-uniform row group

    ull accA[4] = {0, 0, 0, 0};       // cols 2tx, 2tx+1
    ull accB[4] = {0, 0, 0, 0};       // cols 64+2tx, 64+2tx+1

    for (int kc = 0; kc < 2; kc++) {
#pragma unroll
        for (int t = 0; t < 8; t++) {            // W1 chunk [64 x 128]
            int f = tid + t * 256;               // 2048 float4
            int r = f >> 5, c = f & 31;
            *(float4*)&Ws[r * 128 + c * 4] =
                *(const float4*)&W1[(size_t)(kc * 64 + r) * 128 + c * 4];
        }
#pragma unroll
        for (int t = 0; t < 2; t++) {            // x tile [32 x 64], duplicated
            int f = tid + t * 256;               // 512 float4
            int r = f >> 4, c = f & 15;
            float4 v = *(const float4*)&x[(size_t)(row0 + r) * 128 + kc * 64 + c * 4];
            float* dp = &xs2[r * 128 + c * 8];
            *(float4*)&dp[0] = make_float4(v.x, v.x, v.y, v.y);
            *(float4*)&dp[4] = make_float4(v.z, v.z, v.w, v.w);
        }
        __syncthreads();
#pragma unroll 8
        for (int k = 0; k < 64; k++) {
            ull wA = *(ull*)&Ws[k * 128 + tx * 2];
            ull wB = *(ull*)&Ws[k * 128 + 64 + tx * 2];
#pragma unroll
            for (int r = 0; r < 4; r++) {
                ull xv2 = *(ull*)&xs2[(ty + r * 8) * 128 + k * 2];  // broadcast
                fma2(accA[r], xv2, wA);
                fma2(accB[r], xv2, wB);
            }
        }
        __syncthreads();
    }
#pragma unroll
    for (int r = 0; r < 4; r++) {
        int row = row0 + ty + r * 8;
        float dv = g_dis[row];
        float2 a = unpack2(accA[r]);
        float2 b = unpack2(accB[r]);
        *(float2*)&g_G1[(size_t)row * 128 + tx * 2] = make_float2(a.x * dv, a.y * dv);
        *(float2*)&g_G1[(size_t)row * 128 + 64 + tx * 2] = make_float2(b.x * dv, b.y * dv);
    }
}

// ------- conv1 aggregate + fused BN stats: warp per node, grid-stride ------
__global__ __launch_bounds__(256) void k_gather1(const float* __restrict__ b1) {
    __shared__ float ssum[HIDD];
    __shared__ float ssq[HIDD];
    const int tid = threadIdx.x;
    const int wid = tid >> 5;
    const int lane = tid & 31;
    const size_t col = lane * 4;
    if (tid < HIDD) { ssum[tid] = 0.f; ssq[tid] = 0.f; }
    __syncthreads();

    const float4 b1v = *(const float4*)&b1[col];
    float4 psum = make_float4(0.f, 0.f, 0.f, 0.f);
    float4 psq  = make_float4(0.f, 0.f, 0.f, 0.f);

    for (int w = blockIdx.x * 8 + wid; w < NN; w += gridDim.x * 8) {
        float4 acc = *(const float4*)&g_G1[(size_t)w * 128 + col];  // self loop
        int j = g_rowptr[w];
        const int end = g_rowptr[w + 1];
        for (; j + 1 < end; j += 2) {
            int s0 = g_csr[j], s1 = g_csr[j + 1];
            float4 a = *(const float4*)&g_G1[(size_t)s0 * 128 + col];
            float4 b = *(const float4*)&g_G1[(size_t)s1 * 128 + col];
            acc.x += a.x + b.x; acc.y += a.y + b.y;
            acc.z += a.z + b.z; acc.w += a.w + b.w;
        }
        if (j < end) {
            int s0 = g_csr[j];
            float4 a = *(const float4*)&g_G1[(size_t)s0 * 128 + col];
            acc.x += a.x; acc.y += a.y; acc.z += a.z; acc.w += a.w;
        }
        *(float4*)&g_A1[(size_t)w * 128 + col] = acc;
        // BN stats contribution: h = dis[w]*acc + b1
        float dv = g_dis[w];
        float hx = dv * acc.x + b1v.x, hy = dv * acc.y + b1v.y;
        float hz = dv * acc.z + b1v.z, hw = dv * acc.w + b1v.w;
        psum.x += hx; psum.y += hy; psum.z += hz; psum.w += hw;
        psq.x += hx * hx; psq.y += hy * hy; psq.z += hz * hz; psq.w += hw * hw;
    }
    atomicAdd(&ssum[col + 0], psum.x); atomicAdd(&ssum[col + 1], psum.y);
    atomicAdd(&ssum[col + 2], psum.z); atomicAdd(&ssum[col + 3], psum.w);
    atomicAdd(&ssq[col + 0], psq.x);   atomicAdd(&ssq[col + 1], psq.y);
    atomicAdd(&ssq[col + 2], psq.z);   atomicAdd(&ssq[col + 3], psq.w);
    __syncthreads();
    if (tid < HIDD) {
        atomicAdd(&g_sum[tid], ssum[tid]);
        atomicAdd(&g_sumsq[tid], ssq[tid]);
    }
}

__global__ void k_bnfin(const float* __restrict__ gamma, const float* __restrict__ beta) {
    int j = threadIdx.x;
    float mu = g_sum[j] * (1.0f / NN);
    float var = g_sumsq[j] * (1.0f / NN) - mu * mu;
    float inv = rsqrtf(var + EPSV);
    float sc = gamma[j] * inv;
    g_bnscale[j] = sc;
    g_bnshift[j] = beta[j] - mu * sc;
}

// -------- fused BN+ReLU+GEMM2: G2[v]=dis[v]*(relu(bn(h))@W2) (f32x2) -------
__global__ __launch_bounds__(256) void k_gemm2(const float* __restrict__ b1,
                                               const float* __restrict__ W2) {
    __shared__ float W2s[128 * 64];   // 32 KB
    __shared__ float ys2[32 * 256];   // 32 KB (y duplicated)
    const int row0 = blockIdx.x * 32;
    const int tid = threadIdx.x;

#pragma unroll
    for (int t = 0; t < 8; t++) {     // full W2 [128 x 64]
        int f = tid + t * 256;
        *(float4*)&W2s[f * 4] = *(const float4*)&W2[(size_t)f * 4];
    }
    // stage 1: y = relu(bn(dis*A1 + b1)), stored duplicated
#pragma unroll
    for (int t = 0; t < 16; t++) {
        int idx = tid + t * 256;
        int r = idx >> 7, c = idx & 127;
        int row = row0 + r;
        float h = g_dis[row] * g_A1[(size_t)row * 128 + c] + b1[c];
        float y = fmaxf(g_bnscale[c] * h + g_bnshift[c], 0.0f);
        *(float2*)&ys2[r * 256 + c * 2] = make_float2(y, y);
    }
    __syncthreads();

    const int tx = tid & 31;          // cols 2tx, 2tx+1
    const int ty = tid >> 5;          // warp-uniform
    ull acc[4] = {0, 0, 0, 0};
#pragma unroll 8
    for (int k = 0; k < 128; k++) {
        ull w = *(ull*)&W2s[k * 64 + tx * 2];
#pragma unroll
        for (int r = 0; r < 4; r++) {
            ull yv2 = *(ull*)&ys2[(ty + r * 8) * 256 + k * 2];  // broadcast
            fma2(acc[r], yv2, w);
        }
    }
#pragma unroll
    for (int r = 0; r < 4; r++) {
        int row = row0 + ty + r * 8;
        float dv = g_dis[row];
        float2 v = unpack2(acc[r]);
        *(float2*)&g_G2[(size_t)row * 64 + tx * 2] = make_float2(v.x * dv, v.y * dv);
    }
}

// ------------- conv2 aggregate: warp per node, float2 per lane -------------
__global__ __launch_bounds__(256) void k_gather2() {
    int w = (blockIdx.x * blockDim.x + threadIdx.x) >> 5;
    if (w >= NN) return;
    const int lane = threadIdx.x & 31;
    const size_t col = lane * 2;
    float2 acc = *(const float2*)&g_G2[(size_t)w * 64 + col];   // self loop
    int j = g_rowptr[w];
    const int end = g_rowptr[w + 1];
    for (; j + 1 < end; j += 2) {
        int s0 = g_csr[j], s1 = g_csr[j + 1];
        float2 a = *(const float2*)&g_G2[(size_t)s0 * 64 + col];
        float2 b = *(const float2*)&g_G2[(size_t)s1 * 64 + col];
        acc.x += a.x + b.x; acc.y += a.y + b.y;
    }
    if (j < end) {
        int s0 = g_csr[j];
        float2 a = *(const float2*)&g_G2[(size_t)s0 * 64 + col];
        acc.x += a.x; acc.y += a.y;
    }
    *(float2*)&g_A2[(size_t)w * 64 + col] = acc;
}

// ------------- emb + logits + softmax: warp per node (f32x2) ---------------
__global__ __launch_bounds__(128) void k_final(const float* __restrict__ b2,
                                               const float* __restrict__ centers,
                                               const float* __restrict__ temp,
                                               float* __restrict__ out) {
    __shared__ ull cs2[KCL * 33];     // centers as f32x2 pairs, stride 33 (bank-spread)
    __shared__ ull es[4][32];         // per-warp node embedding (pairs)
    const int tid = threadIdx.x;
    const int wid = tid >> 5;
    const int lane = tid & 31;

    for (int i = tid; i < KCL * 32; i += 128) {
        int k = i >> 5, j = i & 31;
        cs2[k * 33 + j] = ((const ull*)centers)[(size_t)k * 32 + j];
    }
    __syncthreads();

    const float invT = 1.0f / temp[0];
    float* emb_out = out;
    float* soft_out = out + (size_t)NN * EMBD;
    const float2 bb = *(const float2*)&b2[lane * 2];

    const int k0 = lane, k1 = lane + 32, k2 = lane + 64;
    const int k3r = lane + 96;
    const int k3 = (k3r < KCL) ? k3r : (KCL - 1);   // compute, maybe discard

    for (int v = blockIdx.x * 4 + wid; v < NN; v += gridDim.x * 4) {
        float dv = g_dis[v];
        float2 a = *(const float2*)&g_A2[(size_t)v * 64 + lane * 2];
        float2 e = make_float2(dv * a.x + bb.x, dv * a.y + bb.y);
        *(float2*)&emb_out[(size_t)v * 64 + lane * 2] = e;
        ull ep;
        asm("mov.b64 %0, {%1, %2};" : "=l"(ep) : "f"(e.x), "f"(e.y));
        __syncwarp();
        es[wid][lane] = ep;
        __syncwarp();

        ull s0 = 0, s1 = 0, s2 = 0, s3 = 0;
#pragma unroll 8
        for (int i = 0; i < 32; i++) {
            ull ei = es[wid][i];                    // broadcast
            fma2(s0, ei, cs2[k0 * 33 + i]);
            fma2(s1, ei, cs2[k1 * 33 + i]);
            fma2(s2, ei, cs2[k2 * 33 + i]);
            fma2(s3, ei, cs2[k3 * 33 + i]);
        }
        float2 f0 = unpack2(s0), f1 = unpack2(s1), f2 = unpack2(s2), f3 = unpack2(s3);
        float lg0 = (f0.x + f0.y) * invT;
        float lg1 = (f1.x + f1.y) * invT;
        float lg2 = (f2.x + f2.y) * invT;
        float lg3 = (k3r < KCL) ? (f3.x + f3.y) * invT : -1e30f;

        float m = fmaxf(fmaxf(lg0, lg1), fmaxf(lg2, lg3));
#pragma unroll
        for (int off = 16; off > 0; off >>= 1)
            m = fmaxf(m, __shfl_xor_sync(0xffffffff, m, off));
        float p0 = __expf(lg0 - m), p1 = __expf(lg1 - m);
        float p2 = __expf(lg2 - m);
        float p3 = (k3r < KCL) ? __expf(lg3 - m) : 0.0f;
        float ps = p0 + p1 + p2 + p3;
#pragma unroll
        for (int off = 16; off > 0; off >>= 1)
            ps += __shfl_xor_sync(0xffffffff, ps, off);
        float rinv = 1.0f / ps;
        float* so = &soft_out[(size_t)v * KCL];
        so[k0] = p0 * rinv;
        so[k1] = p1 * rinv;
        so[k2] = p2 * rinv;
        if (k3r < KCL) so[k3r] = p3 * rinv;
    }
}

// ---------------- launch ----------------
extern "C" void kernel_launch(void* const* d_in, const int* in_sizes, int n_in,
                              void* d_out, int out_size) {
    const float* x       = (const float*)d_in[0];
    const void*  ei      = d_in[1];                 // int32 or int64 (detected)
    const float* W1      = (const float*)d_in[2];
    const float* b1      = (const float*)d_in[3];
    const float* gamma   = (const float*)d_in[4];
    const float* beta    = (const float*)d_in[5];
    const float* W2      = (const float*)d_in[6];
    const float* b2      = (const float*)d_in[7];
    const float* centers = (const float*)d_in[8];
    const float* temp    = (const float*)d_in[9];
    float* out = (float*)d_out;

    k_detect_zero  <<<(NN + 255) / 256, 256>>>((const int*)ei);
    k_extract_count<<<(EE + 255) / 256, 256>>>(ei);
    k_scan         <<<1, 1024>>>();
    k_fill         <<<(EE + 255) / 256, 256>>>();
    k_gemm1        <<<NN / 32, 256>>>(x, W1);
    k_gather1      <<<1184, 256>>>(b1);             // 8 blocks/SM, grid-stride
    k_bnfin        <<<1, 128>>>(gamma, beta);
    k_gemm2        <<<NN / 32, 256>>>(b1, W2);
    k_gather2      <<<(NN * 32 + 255) / 256, 256>>>();
    k_final        <<<1480, 128>>>(b2, centers, temp, out);
}

// round 9
// speedup vs baseline: 1.4188x; 1.4169x over previous
#include <cuda_runtime.h>
#include <cuda_bf16.h>

#define NN 100000
#define EE 1600000
#define IND 128
#define HIDD 128
#define EMBD 64
#define KCL 100
#define EPSV 1e-5f

#define SCAN_B 256
#define NBLK ((NN + SCAN_B - 1) / SCAN_B)   // 391

typedef unsigned long long ull;

// ---------------- scratch (device globals; no allocs allowed) ----------------
__device__ int   g_is64;
__device__ int   g_src[EE];
__device__ int   g_dst[EE];
__device__ int   g_count[NN];
__device__ int   g_bsum[512];
__device__ int   g_boff[512];
__device__ int   g_rowptr[NN + 1];
__device__ int   g_cursor[NN];
__device__ int   g_csr[EE];                 // src ids grouped by dst
__device__ float g_dis[NN];
__device__ float g_G1[(size_t)NN * HIDD];   // (x@W1)[v]  (unscaled)
__device__ float g_A1[(size_t)NN * HIDD];   // conv1 accumulator
__device__ float g_G2[(size_t)NN * EMBD];   // dis[v] * (relu_bn@W2)[v]
__device__ float g_A2[(size_t)NN * EMBD];   // conv2 accumulator
__device__ float g_sum[HIDD];
__device__ float g_sumsq[HIDD];
__device__ float g_bnscale[HIDD];
__device__ float g_bnshift[HIDD];

// ---------------- packed f32x2 helpers (sm_103a FFMA2 path) ----------------
__device__ __forceinline__ void fma2(ull& d, ull a, ull b) {
    asm("fma.rn.f32x2 %0, %1, %2, %0;" : "+l"(d) : "l"(a), "l"(b));
}
__device__ __forceinline__ float2 unpack2(ull v) {
    float2 f;
    asm("mov.b64 {%0, %1}, %2;" : "=f"(f.x), "=f"(f.y) : "l"(v));
    return f;
}

// ---------------- detect dtype + zero counters ----------------
__global__ void k_detect_zero(const int* __restrict__ w) {
    int i = blockIdx.x * blockDim.x + threadIdx.x;
    if (i < NN) g_count[i] = 0;
    if (i < HIDD) { g_sum[i] = 0.0f; g_sumsq[i] = 0.0f; }
    if (i == 0) {
        int any = 0;
        for (int t = 0; t < 128; t++) {
            int idx = 2 * (t * (EE / 128) + 7) + 1;   // odd words only
            any |= w[idx];
        }
        g_is64 = (any == 0) ? 1 : 0;
        g_rowptr[NN] = EE;     // every (clamped) edge lands in some row
    }
}

// ---------------- extract edges (normalize to int32) + count degrees -------
__global__ void k_extract_count(const void* __restrict__ buf) {
    int e = blockIdx.x * blockDim.x + threadIdx.x;
    if (e >= EE) return;
    int s, d;
    if (g_is64) {
        const long long* p = (const long long*)buf;
        s = (int)p[e];
        d = (int)p[(size_t)EE + e];
    } else {
        const int* p = (const int*)buf;
        s = p[e];
        d = p[(size_t)EE + e];
    }
    s = ((unsigned)s < NN) ? s : 0;   // clamp: wrong result beats a trap
    d = ((unsigned)d < NN) ? d : 0;
    g_src[e] = s;
    g_dst[e] = d;
    atomicAdd(&g_count[d], 1);
}

// ---------------- 3-pass coalesced scan of g_count -> rowptr/cursor/dis ----
// Pass A: per-block sums
__global__ __launch_bounds__(SCAN_B) void k_scanA() {
    __shared__ int ws[SCAN_B / 32];
    int i = blockIdx.x * SCAN_B + threadIdx.x;
    int c = (i < NN) ? g_count[i] : 0;
    int v = c;
#pragma unroll
    for (int off = 16; off > 0; off >>= 1) v += __shfl_down_sync(0xffffffff, v, off);
    if ((threadIdx.x & 31) == 0) ws[threadIdx.x >> 5] = v;
    __syncthreads();
    if (threadIdx.x < SCAN_B / 32) {
        int t = ws[threadIdx.x];
#pragma unroll
        for (int off = SCAN_B / 64; off > 0; off >>= 1)
            t += __shfl_down_sync(0xffffffff, t, off, SCAN_B / 32);
        if (threadIdx.x == 0) g_bsum[blockIdx.x] = t;
    }
}

// Pass B: exclusive scan of 391 block sums (single tiny block)
__global__ __launch_bounds__(512) void k_scanB() {
    __shared__ int bs[512];
    int t = threadIdx.x;
    bs[t] = (t < NBLK) ? g_bsum[t] : 0;
    __syncthreads();
#pragma unroll
    for (int off = 1; off < 512; off <<= 1) {
        int v = bs[t];
        int add = (t >= off) ? bs[t - off] : 0;
        __syncthreads();
        bs[t] = v + add;
        __syncthreads();
    }
    g_boff[t] = (t > 0) ? bs[t - 1] : 0;   // exclusive
}

// Pass C: block-local exclusive scan + write rowptr/cursor/dis (coalesced)
__global__ __launch_bounds__(SCAN_B) void k_scanC() {
    __shared__ int bs[SCAN_B];
    int t = threadIdx.x;
    int i = blockIdx.x * SCAN_B + t;
    int c = (i < NN) ? g_count[i] : 0;
    bs[t] = c;
    __syncthreads();
#pragma unroll
    for (int off = 1; off < SCAN_B; off <<= 1) {
        int v = bs[t];
        int add = (t >= off) ? bs[t - off] : 0;
        __syncthreads();
        bs[t] = v + add;
        __syncthreads();
    }
    if (i < NN) {
        int excl = bs[t] - c + g_boff[blockIdx.x];
        g_rowptr[i] = excl;
        g_cursor[i] = excl;
        g_dis[i] = rsqrtf((float)(c + 1));   // +1 self loop
    }
}

__global__ void k_fill() {
    int e = blockIdx.x * blockDim.x + threadIdx.x;
    if (e < EE) {
        int pos = atomicAdd(&g_cursor[g_dst[e]], 1);
        g_csr[pos] = g_src[e];
    }
}

// ---------------- GEMM1: G1[v] = x[v] @ W1 (unscaled; dis applied in gather)
__global__ __launch_bounds__(256) void k_gemm1(const float* __restrict__ x,
                                               const float* __restrict__ W1) {
    __shared__ float Ws[64 * 128];    // 32 KB
    __shared__ float xs2[32 * 128];   // 16 KB (each x value duplicated)
    const int row0 = blockIdx.x * 32;
    const int tid = threadIdx.x;
    const int tx = tid & 31;
    const int ty = tid >> 5;          // warp-uniform row group

    ull accA[4] = {0, 0, 0, 0};       // cols 2tx, 2tx+1
    ull accB[4] = {0, 0, 0, 0};       // cols 64+2tx, 64+2tx+1

    for (int kc = 0; kc < 2; kc++) {
#pragma unroll
        for (int t = 0; t < 8; t++) {            // W1 chunk [64 x 128]
            int f = tid + t * 256;               // 2048 float4
            int r = f >> 5, c = f & 31;
            *(float4*)&Ws[r * 128 + c * 4] =
                *(const float4*)&W1[(size_t)(kc * 64 + r) * 128 + c * 4];
        }
#pragma unroll
        for (int t = 0; t < 2; t++) {            // x tile [32 x 64], duplicated
            int f = tid + t * 256;               // 512 float4
            int r = f >> 4, c = f & 15;
            float4 v = *(const float4*)&x[(size_t)(row0 + r) * 128 + kc * 64 + c * 4];
            float* dp = &xs2[r * 128 + c * 8];
            *(float4*)&dp[0] = make_float4(v.x, v.x, v.y, v.y);
            *(float4*)&dp[4] = make_float4(v.z, v.z, v.w, v.w);
        }
        __syncthreads();
#pragma unroll 8
        for (int k = 0; k < 64; k++) {
            ull wA = *(ull*)&Ws[k * 128 + tx * 2];
            ull wB = *(ull*)&Ws[k * 128 + 64 + tx * 2];
#pragma unroll
            for (int r = 0; r < 4; r++) {
                ull xv2 = *(ull*)&xs2[(ty + r * 8) * 128 + k * 2];  // broadcast
                fma2(accA[r], xv2, wA);
                fma2(accB[r], xv2, wB);
            }
        }
        __syncthreads();
    }
#pragma unroll
    for (int r = 0; r < 4; r++) {
        int row = row0 + ty + r * 8;
        float2 a = unpack2(accA[r]);
        float2 b = unpack2(accB[r]);
        *(float2*)&g_G1[(size_t)row * 128 + tx * 2] = a;
        *(float2*)&g_G1[(size_t)row * 128 + 64 + tx * 2] = b;
    }
}

// ------- conv1 aggregate (dis applied per edge) + fused BN stats -----------
__global__ __launch_bounds__(256) void k_gather1(const float* __restrict__ b1) {
    __shared__ float ssum[HIDD];
    __shared__ float ssq[HIDD];
    const int tid = threadIdx.x;
    const int wid = tid >> 5;
    const int lane = tid & 31;
    const size_t col = lane * 4;
    if (tid < HIDD) { ssum[tid] = 0.f; ssq[tid] = 0.f; }
    __syncthreads();

    const float4 b1v = *(const float4*)&b1[col];
    float4 psum = make_float4(0.f, 0.f, 0.f, 0.f);
    float4 psq  = make_float4(0.f, 0.f, 0.f, 0.f);

    for (int w = blockIdx.x * 8 + wid; w < NN; w += gridDim.x * 8) {
        float dvw = g_dis[w];
        float4 acc = *(const float4*)&g_G1[(size_t)w * 128 + col];  // self loop
        acc.x *= dvw; acc.y *= dvw; acc.z *= dvw; acc.w *= dvw;
        int j = g_rowptr[w];
        const int end = g_rowptr[w + 1];
        for (; j + 1 < end; j += 2) {
            int s0 = g_csr[j], s1 = g_csr[j + 1];
            float d0 = g_dis[s0], d1 = g_dis[s1];
            float4 a = *(const float4*)&g_G1[(size_t)s0 * 128 + col];
            float4 b = *(const float4*)&g_G1[(size_t)s1 * 128 + col];
            acc.x += d0 * a.x + d1 * b.x; acc.y += d0 * a.y + d1 * b.y;
            acc.z += d0 * a.z + d1 * b.z; acc.w += d0 * a.w + d1 * b.w;
        }
        if (j < end) {
            int s0 = g_csr[j];
            float d0 = g_dis[s0];
            float4 a = *(const float4*)&g_G1[(size_t)s0 * 128 + col];
            acc.x += d0 * a.x; acc.y += d0 * a.y;
            acc.z += d0 * a.z; acc.w += d0 * a.w;
        }
        *(float4*)&g_A1[(size_t)w * 128 + col] = acc;
        // BN stats contribution: h = dis[w]*acc + b1
        float hx = dvw * acc.x + b1v.x, hy = dvw * acc.y + b1v.y;
        float hz = dvw * acc.z + b1v.z, hw = dvw * acc.w + b1v.w;
        psum.x += hx; psum.y += hy; psum.z += hz; psum.w += hw;
        psq.x += hx * hx; psq.y += hy * hy; psq.z += hz * hz; psq.w += hw * hw;
    }
    atomicAdd(&ssum[col + 0], psum.x); atomicAdd(&ssum[col + 1], psum.y);
    atomicAdd(&ssum[col + 2], psum.z); atomicAdd(&ssum[col + 3], psum.w);
    atomicAdd(&ssq[col + 0], psq.x);   atomicAdd(&ssq[col + 1], psq.y);
    atomicAdd(&ssq[col + 2], psq.z);   atomicAdd(&ssq[col + 3], psq.w);
    __syncthreads();
    if (tid < HIDD) {
        atomicAdd(&g_sum[tid], ssum[tid]);
        atomicAdd(&g_sumsq[tid], ssq[tid]);
    }
}

__global__ void k_bnfin(const float* __restrict__ gamma, const float* __restrict__ beta) {
    int j = threadIdx.x;
    float mu = g_sum[j] * (1.0f / NN);
    float var = g_sumsq[j] * (1.0f / NN) - mu * mu;
    float inv = rsqrtf(var + EPSV);
    float sc = gamma[j] * inv;
    g_bnscale[j] = sc;
    g_bnshift[j] = beta[j] - mu * sc;
}

// -------- fused BN+ReLU+GEMM2: G2[v]=dis[v]*(relu(bn(h))@W2) (f32x2) -------
__global__ __launch_bounds__(256) void k_gemm2(const float* __restrict__ b1,
                                               const float* __restrict__ W2) {
    __shared__ float W2s[128 * 64];   // 32 KB
    __shared__ float ys2[32 * 256];   // 32 KB (y duplicated)
    const int row0 = blockIdx.x * 32;
    const int tid = threadIdx.x;

#pragma unroll
    for (int t = 0; t < 8; t++) {     // full W2 [128 x 64]
        int f = tid + t * 256;
        *(float4*)&W2s[f * 4] = *(const float4*)&W2[(size_t)f * 4];
    }
    // stage 1: y = relu(bn(dis*A1 + b1)), stored duplicated
#pragma unroll
    for (int t = 0; t < 16; t++) {
        int idx = tid + t * 256;
        int r = idx >> 7, c = idx & 127;
        int row = row0 + r;
        float h = g_dis[row] * g_A1[(size_t)row * 128 + c] + b1[c];
        float y = fmaxf(g_bnscale[c] * h + g_bnshift[c], 0.0f);
        *(float2*)&ys2[r * 256 + c * 2] = make_float2(y, y);
    }
    __syncthreads();

    const int tx = tid & 31;          // cols 2tx, 2tx+1
    const int ty = tid >> 5;          // warp-uniform
    ull acc[4] = {0, 0, 0, 0};
#pragma unroll 8
    for (int k = 0; k < 128; k++) {
        ull w = *(ull*)&W2s[k * 64 + tx * 2];
#pragma unroll
        for (int r = 0; r < 4; r++) {
            ull yv2 = *(ull*)&ys2[(ty + r * 8) * 256 + k * 2];  // broadcast
            fma2(acc[r], yv2, w);
        }
    }
#pragma unroll
    for (int r = 0; r < 4; r++) {
        int row = row0 + ty + r * 8;
        float dv = g_dis[row];
        float2 v = unpack2(acc[r]);
        *(float2*)&g_G2[(size_t)row * 64 + tx * 2] = make_float2(v.x * dv, v.y * dv);
    }
}

// ------------- conv2 aggregate: warp per node, float2 per lane -------------
__global__ __launch_bounds__(256) void k_gather2() {
    int w = (blockIdx.x * blockDim.x + threadIdx.x) >> 5;
    if (w >= NN) return;
    const int lane = threadIdx.x & 31;
    const size_t col = lane * 2;
    float2 acc = *(const float2*)&g_G2[(size_t)w * 64 + col];   // self loop
    int j = g_rowptr[w];
    const int end = g_rowptr[w + 1];
    for (; j + 1 < end; j += 2) {
        int s0 = g_csr[j], s1 = g_csr[j + 1];
        float2 a = *(const float2*)&g_G2[(size_t)s0 * 64 + col];
        float2 b = *(const float2*)&g_G2[(size_t)s1 * 64 + col];
        acc.x += a.x + b.x; acc.y += a.y + b.y;
    }
    if (j < end) {
        int s0 = g_csr[j];
        float2 a = *(const float2*)&g_G2[(size_t)s0 * 64 + col];
        acc.x += a.x; acc.y += a.y;
    }
    *(float2*)&g_A2[(size_t)w * 64 + col] = acc;
}

// ------------- emb + logits + softmax: warp per node (f32x2) ---------------
__global__ __launch_bounds__(128) void k_final(const float* __restrict__ b2,
                                               const float* __restrict__ centers,
                                               const float* __restrict__ temp,
                                               float* __restrict__ out) {
    __shared__ ull cs2[KCL * 33];     // centers as f32x2 pairs, stride 33
    __shared__ ull es[4][32];         // per-warp node embedding (pairs)
    const int tid = threadIdx.x;
    const int wid = tid >> 5;
    const int lane = tid & 31;

    for (int i = tid; i < KCL * 32; i += 128) {
        int k = i >> 5, j = i & 31;
        cs2[k * 33 + j] = ((const ull*)centers)[(size_t)k * 32 + j];
    }
    __syncthreads();

    const float invT = 1.0f / temp[0];
    float* emb_out = out;
    float* soft_out = out + (size_t)NN * EMBD;
    const float2 bb = *(const float2*)&b2[lane * 2];

    const int k0 = lane, k1 = lane + 32, k2 = lane + 64;
    const int k3r = lane + 96;
    const int k3 = (k3r < KCL) ? k3r : (KCL - 1);   // compute, maybe discard

    for (int v = blockIdx.x * 4 + wid; v < NN; v += gridDim.x * 4) {
        float dv = g_dis[v];
        float2 a = *(const float2*)&g_A2[(size_t)v * 64 + lane * 2];
        float2 e = make_float2(dv * a.x + bb.x, dv * a.y + bb.y);
        *(float2*)&emb_out[(size_t)v * 64 + lane * 2] = e;
        ull ep;
        asm("mov.b64 %0, {%1, %2};" : "=l"(ep) : "f"(e.x), "f"(e.y));
        __syncwarp();
        es[wid][lane] = ep;
        __syncwarp();

        ull s0 = 0, s1 = 0, s2 = 0, s3 = 0;
#pragma unroll 8
        for (int i = 0; i < 32; i++) {
            ull ei = es[wid][i];                    // broadcast
            fma2(s0, ei, cs2[k0 * 33 + i]);
            fma2(s1, ei, cs2[k1 * 33 + i]);
            fma2(s2, ei, cs2[k2 * 33 + i]);
            fma2(s3, ei, cs2[k3 * 33 + i]);
        }
        float2 f0 = unpack2(s0), f1 = unpack2(s1), f2 = unpack2(s2), f3 = unpack2(s3);
        float lg0 = (f0.x + f0.y) * invT;
        float lg1 = (f1.x + f1.y) * invT;
        float lg2 = (f2.x + f2.y) * invT;
        float lg3 = (k3r < KCL) ? (f3.x + f3.y) * invT : -1e30f;

        float m = fmaxf(fmaxf(lg0, lg1), fmaxf(lg2, lg3));
#pragma unroll
        for (int off = 16; off > 0; off >>= 1)
            m = fmaxf(m, __shfl_xor_sync(0xffffffff, m, off));
        float p0 = __expf(lg0 - m), p1 = __expf(lg1 - m);
        float p2 = __expf(lg2 - m);
        float p3 = (k3r < KCL) ? __expf(lg3 - m) : 0.0f;
        float ps = p0 + p1 + p2 + p3;
#pragma unroll
        for (int off = 16; off > 0; off >>= 1)
            ps += __shfl_xor_sync(0xffffffff, ps, off);
        float rinv = 1.0f / ps;
        float* so = &soft_out[(size_t)v * KCL];
        so[k0] = p0 * rinv;
        so[k1] = p1 * rinv;
        so[k2] = p2 * rinv;
        if (k3r < KCL) so[k3r] = p3 * rinv;
    }
}

// ---------------- launch ----------------
extern "C" void kernel_launch(void* const* d_in, const int* in_sizes, int n_in,
                              void* d_out, int out_size) {
    const float* x       = (const float*)d_in[0];
    const void*  ei      = d_in[1];                 // int32 or int64 (detected)
    const float* W1      = (const float*)d_in[2];
    const float* b1      = (const float*)d_in[3];
    const float* gamma   = (const float*)d_in[4];
    const float* beta    = (const float*)d_in[5];
    const float* W2      = (const float*)d_in[6];
    const float* b2      = (const float*)d_in[7];
    const float* centers = (const float*)d_in[8];
    const float* temp    = (const float*)d_in[9];
    float* out = (float*)d_out;

    k_detect_zero  <<<(NN + 255) / 256, 256>>>((const int*)ei);
    k_extract_count<<<(EE + 255) / 256, 256>>>(ei);
    k_scanA        <<<NBLK, SCAN_B>>>();
    k_gemm1        <<<NN / 32, 256>>>(x, W1);       // launch idx 3: profiled
    k_scanB        <<<1, 512>>>();
    k_scanC        <<<NBLK, SCAN_B>>>();
    k_fill         <<<(EE + 255) / 256, 256>>>();
    k_gather1      <<<1184, 256>>>(b1);             // 8 warps/block, grid-stride
    k_bnfin        <<<1, 128>>>(gamma, beta);
    k_gemm2        <<<NN / 32, 256>>>(b1, W2);
    k_gather2      <<<(NN * 32 + 255) / 256, 256>>>();
    k_final        <<<1480, 128>>>(b2, centers, temp, out);
}

// round 11
// speedup vs baseline: 1.5109x; 1.0649x over previous
#include <cuda_runtime.h>
#include <cuda_bf16.h>

#define NN 100000
#define EE 1600000
#define IND 128
#define HIDD 128
#define EMBD 64
#define KCL 100
#define EPSV 1e-5f

#define SCAN_B 256
#define NBLK ((NN + SCAN_B - 1) / SCAN_B)   // 391
#define GBLK ((NN + 63) / 64)               // 1563 (64-row gemm tiles)

typedef unsigned long long ull;

// ---------------- scratch (device globals; no allocs allowed) ----------------
__device__ int   g_is64;
__device__ int   g_src[EE];
__device__ int   g_dst[EE];
__device__ int   g_count[NN];
__device__ int   g_bsum[512];
__device__ int   g_boff[512];
__device__ int   g_rowptr[NN + 1];
__device__ int   g_cursor[NN];
__device__ int   g_csr[EE];                 // src ids grouped by dst
__device__ float g_dis[NN];
__device__ float g_G1[(size_t)NN * HIDD];   // (x@W1)[v]  (unscaled)
__device__ float g_A1[(size_t)NN * HIDD];   // conv1 accumulator
__device__ float g_G2[(size_t)NN * EMBD];   // dis[v] * (relu_bn@W2)[v]
__device__ float g_sum[HIDD];
__device__ float g_sumsq[HIDD];
__device__ float g_bnscale[HIDD];
__device__ float g_bnshift[HIDD];

// ---------------- packed f32x2 helpers (sm_103a FFMA2 path) ----------------
__device__ __forceinline__ void fma2(ull& d, ull a, ull b) {
    asm("fma.rn.f32x2 %0, %1, %2, %0;" : "+l"(d) : "l"(a), "l"(b));
}
__device__ __forceinline__ float2 unpack2(ull v) {
    float2 f;
    asm("mov.b64 {%0, %1}, %2;" : "=f"(f.x), "=f"(f.y) : "l"(v));
    return f;
}

// ---------------- detect dtype + zero counters ----------------
__global__ void k_detect_zero(const int* __restrict__ w) {
    int i = blockIdx.x * blockDim.x + threadIdx.x;
    if (i < NN) g_count[i] = 0;
    if (i < HIDD) { g_sum[i] = 0.0f; g_sumsq[i] = 0.0f; }
    if (i == 0) {
        int any = 0;
        for (int t = 0; t < 128; t++) {
            int idx = 2 * (t * (EE / 128) + 7) + 1;   // odd words only
            any |= w[idx];
        }
        g_is64 = (any == 0) ? 1 : 0;
        g_rowptr[NN] = EE;     // every (clamped) edge lands in some row
    }
}

// ---------------- extract edges (normalize to int32) + count degrees -------
__global__ void k_extract_count(const void* __restrict__ buf) {
    int e = blockIdx.x * blockDim.x + threadIdx.x;
    if (e >= EE) return;
    int s, d;
    if (g_is64) {
        const long long* p = (const long long*)buf;
        s = (int)p[e];
        d = (int)p[(size_t)EE + e];
    } else {
        const int* p = (const int*)buf;
        s = p[e];
        d = p[(size_t)EE + e];
    }
    s = ((unsigned)s < NN) ? s : 0;   // clamp: wrong result beats a trap
    d = ((unsigned)d < NN) ? d : 0;
    g_src[e] = s;
    g_dst[e] = d;
    atomicAdd(&g_count[d], 1);
}

// ---------------- 3-pass coalesced scan of g_count -> rowptr/cursor/dis ----
__global__ __launch_bounds__(SCAN_B) void k_scanA() {
    __shared__ int ws[SCAN_B / 32];
    int i = blockIdx.x * SCAN_B + threadIdx.x;
    int c = (i < NN) ? g_count[i] : 0;
    int v = c;
#pragma unroll
    for (int off = 16; off > 0; off >>= 1) v += __shfl_down_sync(0xffffffff, v, off);
    if ((threadIdx.x & 31) == 0) ws[threadIdx.x >> 5] = v;
    __syncthreads();
    if (threadIdx.x < SCAN_B / 32) {
        int t = ws[threadIdx.x];
#pragma unroll
        for (int off = SCAN_B / 64; off > 0; off >>= 1)
            t += __shfl_down_sync(0xffffffff, t, off, SCAN_B / 32);
        if (threadIdx.x == 0) g_bsum[blockIdx.x] = t;
    }
}

__global__ __launch_bounds__(512) void k_scanB() {
    __shared__ int bs[512];
    int t = threadIdx.x;
    bs[t] = (t < NBLK) ? g_bsum[t] : 0;
    __syncthreads();
#pragma unroll
    for (int off = 1; off < 512; off <<= 1) {
        int v = bs[t];
        int add = (t >= off) ? bs[t - off] : 0;
        __syncthreads();
        bs[t] = v + add;
        __syncthreads();
    }
    g_boff[t] = (t > 0) ? bs[t - 1] : 0;   // exclusive
}

__global__ __launch_bounds__(SCAN_B) void k_scanC() {
    __shared__ int bs[SCAN_B];
    int t = threadIdx.x;
    int i = blockIdx.x * SCAN_B + t;
    int c = (i < NN) ? g_count[i] : 0;
    bs[t] = c;
    __syncthreads();
#pragma unroll
    for (int off = 1; off < SCAN_B; off <<= 1) {
        int v = bs[t];
        int add = (t >= off) ? bs[t - off] : 0;
        __syncthreads();
        bs[t] = v + add;
        __syncthreads();
    }
    if (i < NN) {
        int excl = bs[t] - c + g_boff[blockIdx.x];
        g_rowptr[i] = excl;
        g_cursor[i] = excl;
        g_dis[i] = rsqrtf((float)(c + 1));   // +1 self loop
    }
}

__global__ void k_fill() {
    int e = blockIdx.x * blockDim.x + threadIdx.x;
    if (e < EE) {
        int pos = atomicAdd(&g_cursor[g_dst[e]], 1);
        g_csr[pos] = g_src[e];
    }
}

// -------- GEMM1: G1[v] = x[v] @ W1 ; 64-row tiles, 8 rows/thread -----------
// Per inner k-step: 2 distinct LDS.64 (W) amortized over 16 FFMA2.
__global__ __launch_bounds__(256) void k_gemm1(const float* __restrict__ x,
                                               const float* __restrict__ W1) {
    __shared__ float Ws[32 * 128];    // 16 KB (k-chunk 32)
    __shared__ float xs2[64 * 64];    // 16 KB (x dup: 32 k-vals x2)
    const int row0 = blockIdx.x * 64;
    const int tid = threadIdx.x;
    const int tx = tid & 31;
    const int ty = tid >> 5;          // warp-uniform

    ull accA[8] = {0,0,0,0,0,0,0,0};  // cols 2tx, 2tx+1
    ull accB[8] = {0,0,0,0,0,0,0,0};  // cols 64+2tx, 64+2tx+1

    for (int kc = 0; kc < 4; kc++) {
#pragma unroll
        for (int t = 0; t < 4; t++) {            // W1 chunk [32 x 128] = 1024 f4
            int f = tid + t * 256;
            int r = f >> 5, c = f & 31;
            *(float4*)&Ws[r * 128 + c * 4] =
                *(const float4*)&W1[(size_t)(kc * 32 + r) * 128 + c * 4];
        }
#pragma unroll
        for (int t = 0; t < 2; t++) {            // x tile [64 x 32] dup = 512 f4
            int f = tid + t * 256;
            int r = f >> 3, c = f & 7;
            int row = row0 + r;
            int rowc = (row < NN) ? row : (NN - 1);
            float4 v = *(const float4*)&x[(size_t)rowc * 128 + kc * 32 + c * 4];
            float* dp = &xs2[r * 64 + c * 8];
            *(float4*)&dp[0] = make_float4(v.x, v.x, v.y, v.y);
            *(float4*)&dp[4] = make_float4(v.z, v.z, v.w, v.w);
        }
        __syncthreads();
#pragma unroll 8
        for (int k = 0; k < 32; k++) {
            ull wA = *(ull*)&Ws[k * 128 + tx * 2];
            ull wB = *(ull*)&Ws[k * 128 + 64 + tx * 2];
#pragma unroll
            for (int r = 0; r < 8; r++) {
                ull xv2 = *(ull*)&xs2[(ty + r * 8) * 64 + k * 2];  // broadcast
                fma2(accA[r], xv2, wA);
                fma2(accB[r], xv2, wB);
            }
        }
        __syncthreads();
    }
#pragma unroll
    for (int r = 0; r < 8; r++) {
        int row = row0 + ty + r * 8;
        if (row < NN) {
            *(float2*)&g_G1[(size_t)row * 128 + tx * 2] = unpack2(accA[r]);
            *(float2*)&g_G1[(size_t)row * 128 + 64 + tx * 2] = unpack2(accB[r]);
        }
    }
}

// ------- conv1 aggregate (dis applied per edge) + fused BN stats -----------
__global__ __launch_bounds__(256) void k_gather1(const float* __restrict__ b1) {
    __shared__ float ssum[HIDD];
    __shared__ float ssq[HIDD];
    const int tid = threadIdx.x;
    const int wid = tid >> 5;
    const int lane = tid & 31;
    const size_t col = lane * 4;
    if (tid < HIDD) { ssum[tid] = 0.f; ssq[tid] = 0.f; }
    __syncthreads();

    const float4 b1v = *(const float4*)&b1[col];
    float4 psum = make_float4(0.f, 0.f, 0.f, 0.f);
    float4 psq  = make_float4(0.f, 0.f, 0.f, 0.f);

    for (int w = blockIdx.x * 8 + wid; w < NN; w += gridDim.x * 8) {
        float dvw = g_dis[w];
        float4 acc = *(const float4*)&g_G1[(size_t)w * 128 + col];  // self loop
        acc.x *= dvw; acc.y *= dvw; acc.z *= dvw; acc.w *= dvw;
        int j = g_rowptr[w];
        const int end = g_rowptr[w + 1];
        for (; j + 1 < end; j += 2) {
            int s0 = g_csr[j], s1 = g_csr[j + 1];
            float d0 = g_dis[s0], d1 = g_dis[s1];
            float4 a = *(const float4*)&g_G1[(size_t)s0 * 128 + col];
            float4 b = *(const float4*)&g_G1[(size_t)s1 * 128 + col];
            acc.x += d0 * a.x + d1 * b.x; acc.y += d0 * a.y + d1 * b.y;
            acc.z += d0 * a.z + d1 * b.z; acc.w += d0 * a.w + d1 * b.w;
        }
        if (j < end) {
            int s0 = g_csr[j];
            float d0 = g_dis[s0];
            float4 a = *(const float4*)&g_G1[(size_t)s0 * 128 + col];
            acc.x += d0 * a.x; acc.y += d0 * a.y;
            acc.z += d0 * a.z; acc.w += d0 * a.w;
        }
        *(float4*)&g_A1[(size_t)w * 128 + col] = acc;
        float hx = dvw * acc.x + b1v.x, hy = dvw * acc.y + b1v.y;
        float hz = dvw * acc.z + b1v.z, hw = dvw * acc.w + b1v.w;
        psum.x += hx; psum.y += hy; psum.z += hz; psum.w += hw;
        psq.x += hx * hx; psq.y += hy * hy; psq.z += hz * hz; psq.w += hw * hw;
    }
    atomicAdd(&ssum[col + 0], psum.x); atomicAdd(&ssum[col + 1], psum.y);
    atomicAdd(&ssum[col + 2], psum.z); atomicAdd(&ssum[col + 3], psum.w);
    atomicAdd(&ssq[col + 0], psq.x);   atomicAdd(&ssq[col + 1], psq.y);
    atomicAdd(&ssq[col + 2], psq.z);   atomicAdd(&ssq[col + 3], psq.w);
    __syncthreads();
    if (tid < HIDD) {
        atomicAdd(&g_sum[tid], ssum[tid]);
        atomicAdd(&g_sumsq[tid], ssq[tid]);
    }
}

__global__ void k_bnfin(const float* __restrict__ gamma, const float* __restrict__ beta) {
    int j = threadIdx.x;
    float mu = g_sum[j] * (1.0f / NN);
    float var = g_sumsq[j] * (1.0f / NN) - mu * mu;
    float inv = rsqrtf(var + EPSV);
    float sc = gamma[j] * inv;
    g_bnscale[j] = sc;
    g_bnshift[j] = beta[j] - mu * sc;
}

// --- fused BN+ReLU+GEMM2: 64-row tiles, 8 rows/thread, k-chunk 64 ----------
__global__ __launch_bounds__(256) void k_gemm2(const float* __restrict__ b1,
                                               const float* __restrict__ W2) {
    __shared__ float W2s[64 * 64];    // 16 KB (k-chunk 64 x 64 cols)
    __shared__ float ys2[64 * 128];   // 32 KB (y dup: 64 k-vals x2)
    const int row0 = blockIdx.x * 64;
    const int tid = threadIdx.x;
    const int tx = tid & 31;          // cols 2tx, 2tx+1
    const int ty = tid >> 5;          // warp-uniform

    ull acc[8] = {0,0,0,0,0,0,0,0};

    for (int kc = 0; kc < 2; kc++) {
#pragma unroll
        for (int t = 0; t < 4; t++) {            // W2 chunk [64 x 64] = 1024 f4
            int f = tid + t * 256;
            int r = f >> 4, c = f & 15;
            *(float4*)&W2s[r * 64 + c * 4] =
                *(const float4*)&W2[(size_t)(kc * 64 + r) * 64 + c * 4];
        }
        // y = relu(bn(dis*A1 + b1)) for cols kc*64..+63, stored duplicated
#pragma unroll
        for (int t = 0; t < 16; t++) {
            int idx = tid + t * 256;
            int r = idx >> 6, c = idx & 63;
            int row = row0 + r;
            int rowc = (row < NN) ? row : (NN - 1);
            int cc = kc * 64 + c;
            float h = g_dis[rowc] * g_A1[(size_t)rowc * 128 + cc] + b1[cc];
            float y = fmaxf(g_bnscale[cc] * h + g_bnshift[cc], 0.0f);
            *(float2*)&ys2[r * 128 + c * 2] = make_float2(y, y);
        }
        __syncthreads();
#pragma unroll 8
        for (int k = 0; k < 64; k++) {
            ull w = *(ull*)&W2s[k * 64 + tx * 2];
#pragma unroll
            for (int r = 0; r < 8; r++) {
                ull yv2 = *(ull*)&ys2[(ty + r * 8) * 128 + k * 2];  // broadcast
                fma2(acc[r], yv2, w);
            }
        }
        __syncthreads();
    }
#pragma unroll
    for (int r = 0; r < 8; r++) {
        int row = row0 + ty + r * 8;
        if (row < NN) {
            float dv = g_dis[row];
            float2 v = unpack2(acc[r]);
            *(float2*)&g_G2[(size_t)row * 64 + tx * 2] = make_float2(v.x * dv, v.y * dv);
        }
    }
}

// ---- fused conv2 gather + emb + logits + softmax: warp per node -----------
__global__ __launch_bounds__(256) void k_final(const float* __restrict__ b2,
                                               const float* __restrict__ centers,
                                               const float* __restrict__ temp,
                                               float* __restrict__ out) {
    __shared__ ull cs2[KCL * 33];     // centers as f32x2 pairs, stride 33
    __shared__ ull es[8][32];         // per-warp node embedding (pairs)
    const int tid = threadIdx.x;
    const int wid = tid >> 5;
    const int lane = tid & 31;

    for (int i = tid; i < KCL * 32; i += 256) {
        int k = i >> 5, j = i & 31;
        cs2[k * 33 + j] = ((const ull*)centers)[(size_t)k * 32 + j];
    }
    __syncthreads();

    const float invT = 1.0f / temp[0];
    float* emb_out = out;
    float* soft_out = out + (size_t)NN * EMBD;
    const float2 bb = *(const float2*)&b2[lane * 2];
    const size_t col = lane * 2;

    const int k0 = lane, k1 = lane + 32, k2 = lane + 64;
    const int k3r = lane + 96;
    const int k3 = (k3r < KCL) ? k3r : (KCL - 1);   // compute, maybe discard

    for (int v = blockIdx.x * 8 + wid; v < NN; v += gridDim.x * 8) {
        // conv2 gather (registers only; no A2 round-trip)
        float2 acc = *(const float2*)&g_G2[(size_t)v * 64 + col];   // self loop
        int j = g_rowptr[v];
        const int end = g_rowptr[v + 1];
        for (; j + 1 < end; j += 2) {
            int s0 = g_csr[j], s1 = g_csr[j + 1];
            float2 a = *(const float2*)&g_G2[(size_t)s0 * 64 + col];
            float2 b = *(const float2*)&g_G2[(size_t)s1 * 64 + col];
            acc.x += a.x + b.x; acc.y += a.y + b.y;
        }
        if (j < end) {
            int s0 = g_csr[j];
            float2 a = *(const float2*)&g_G2[(size_t)s0 * 64 + col];
            acc.x += a.x; acc.y += a.y;
        }

        float dv = g_dis[v];
        float2 e = make_float2(dv * acc.x + bb.x, dv * acc.y + bb.y);
        *(float2*)&emb_out[(size_t)v * 64 + col] = e;
        ull ep;
        asm("mov.b64 %0, {%1, %2};" : "=l"(ep) : "f"(e.x), "f"(e.y));
        __syncwarp();
        es[wid][lane] = ep;
        __syncwarp();

        ull s0 = 0, s1 = 0, s2 = 0, s3 = 0;
#pragma unroll 8
        for (int i = 0; i < 32; i++) {
            ull ei = es[wid][i];                    // broadcast
            fma2(s0, ei, cs2[k0 * 33 + i]);
            fma2(s1, ei, cs2[k1 * 33 + i]);
            fma2(s2, ei, cs2[k2 * 33 + i]);
            fma2(s3, ei, cs2[k3 * 33 + i]);
        }
        float2 f0 = unpack2(s0), f1 = unpack2(s1), f2 = unpack2(s2), f3 = unpack2(s3);
        float lg0 = (f0.x + f0.y) * invT;
        float lg1 = (f1.x + f1.y) * invT;
        float lg2 = (f2.x + f2.y) * invT;
        float lg3 = (k3r < KCL) ? (f3.x + f3.y) * invT : -1e30f;

        float m = fmaxf(fmaxf(lg0, lg1), fmaxf(lg2, lg3));
#pragma unroll
        for (int off = 16; off > 0; off >>= 1)
            m = fmaxf(m, __shfl_xor_sync(0xffffffff, m, off));
        float p0 = __expf(lg0 - m), p1 = __expf(lg1 - m);
        float p2 = __expf(lg2 - m);
        float p3 = (k3r < KCL) ? __expf(lg3 - m) : 0.0f;
        float ps = p0 + p1 + p2 + p3;
#pragma unroll
        for (int off = 16; off > 0; off >>= 1)
            ps += __shfl_xor_sync(0xffffffff, ps, off);
        float rinv = 1.0f / ps;
        float* so = &soft_out[(size_t)v * KCL];
        so[k0] = p0 * rinv;
        so[k1] = p1 * rinv;
        so[k2] = p2 * rinv;
        if (k3r < KCL) so[k3r] = p3 * rinv;
    }
}

// ---------------- launch ----------------
extern "C" void kernel_launch(void* const* d_in, const int* in_sizes, int n_in,
                              void* d_out, int out_size) {
    const float* x       = (const float*)d_in[0];
    const void*  ei      = d_in[1];                 // int32 or int64 (detected)
    const float* W1      = (const float*)d_in[2];
    const float* b1      = (const float*)d_in[3];
    const float* gamma   = (const float*)d_in[4];
    const float* beta    = (const float*)d_in[5];
    const float* W2      = (const float*)d_in[6];
    const float* b2      = (const float*)d_in[7];
    const float* centers = (const float*)d_in[8];
    const float* temp    = (const float*)d_in[9];
    float* out = (float*)d_out;

    k_detect_zero  <<<(NN + 255) / 256, 256>>>((const int*)ei);
    k_extract_count<<<(EE + 255) / 256, 256>>>(ei);
    k_scanA        <<<NBLK, SCAN_B>>>();
    k_gemm1        <<<GBLK, 256>>>(x, W1);          // launch idx 3: profiled
    k_scanB        <<<1, 512>>>();
    k_scanC        <<<NBLK, SCAN_B>>>();
    k_fill         <<<(EE + 255) / 256, 256>>>();
    k_gather1      <<<1184, 256>>>(b1);             // 8 warps/block, grid-stride
    k_bnfin        <<<1, 128>>>(gamma, beta);
    k_gemm2        <<<GBLK, 256>>>(b1, W2);
    k_final        <<<1184, 256>>>(b2, centers, temp, out);   // fused gather2+final
}